// round 14
// baseline (speedup 1.0000x reference)
#include <cuda_runtime.h>
#include <cuda_fp16.h>

// ---------------------------------------------------------------------------
// GCN 2-layer, round 14: 3 launches.
//   k_edges : prep+scan+sums+fill fused via grid barriers
//   k_pool  : tf32 TC gemm1, cp.async double-buffered (KC=16)
//   k_tail  : [gather1+gemm2] -> gridbar -> [gather2+softmax]; h2 in fp16
// ---------------------------------------------------------------------------

#define MAXN 131072
#define MAXE 4194304
#define IN_CH 256
#define HID 64
#define OUT_CH 16

__device__ __half2 g_h1h[(size_t)MAXN * 32];   // h1 fp16, 128B per row
__device__ __half2 g_h2h[(size_t)MAXN * 8];    // h2 fp16, 32B per row
__device__ float g_dinv[MAXN];
__device__ int   g_incnt[MAXN];      // zero at entry (static init / tail phase-2)
__device__ int   g_rowstart[MAXN];
__device__ int   g_fill[MAXN];       // zero at entry (same mechanism)
__device__ int   g_blocksum[1024];
__device__ int2  g_edge[MAXE];
__device__ int2  g_csr[MAXE];        // (src, norm-bits) grouped by dst
__device__ unsigned g_barcnt;        // grid barrier arrive count (self-resetting)
__device__ volatile unsigned g_bargen;  // generation (monotonic)

__device__ __forceinline__ int rowstart(int i) {
    return g_rowstart[i] + g_blocksum[i >> 8];
}

__device__ __forceinline__ void gridbar(unsigned nb) {
    __syncthreads();
    if (threadIdx.x == 0) {
        __threadfence();
        unsigned gen = g_bargen;
        unsigned t = atomicAdd(&g_barcnt, 1u);
        if (t == nb - 1) {
            g_barcnt = 0;
            __threadfence();
            g_bargen = gen + 1;
        } else {
            while (g_bargen == gen) __nanosleep(40);
        }
        __threadfence();
    }
    __syncthreads();
}

// ---- k_edges: fused prep + scan + sums-scan + fill ------------------------
__global__ __launch_bounds__(256, 6) void k_edges(const void* __restrict__ ei,
                                                  int N, long long E,
                                                  int nwords, int nbS) {
    __shared__ int s_is64;
    __shared__ int wsum[8];
    __shared__ int sA[512], sB[512];
    int tid = threadIdx.x;
    unsigned bid = blockIdx.x, nb = gridDim.x;
    int lane = tid & 31, wid = tid >> 5;

    {
        const long long* p = (const long long*)ei;
        int ok = 1;
        #pragma unroll
        for (int j = 0; j < 2; j++) {
            int wd = tid + j * 256;
            if (wd < nwords) {
                long long v = __ldg(p + wd);
                if (v < 0 || v >= (long long)N) ok = 0;
            }
        }
        int all = __syncthreads_and(ok);
        if (tid == 0) s_is64 = all;
    }
    __syncthreads();
    int is64 = s_is64;

    // phase 1: decode edges + in-degree
    for (long long e = (long long)bid * 256 + tid; e < E; e += (long long)nb * 256) {
        int s, d;
        if (is64) {
            s = (int)__ldg(((const long long*)ei) + e);
            d = (int)__ldg(((const long long*)ei) + E + e);
        } else {
            s = __ldg(((const int*)ei) + e);
            d = __ldg(((const int*)ei) + E + e);
        }
        g_edge[e] = make_int2(s, d);
        atomicAdd(&g_incnt[d], 1);
    }
    gridbar(nb);

    // phase 2: per-256-chunk scans + dinv
    for (int cb = bid; cb < nbS; cb += nb) {
        int i = cb * 256 + tid;
        int v = (i < N) ? g_incnt[i] : 0;
        if (i < N) g_dinv[i] = rsqrtf((float)(v + 1));
        int xv = v;
        #pragma unroll
        for (int o = 1; o < 32; o <<= 1) {
            int y = __shfl_up_sync(0xffffffffu, xv, o);
            if (lane >= o) xv += y;
        }
        if (lane == 31) wsum[wid] = xv;
        __syncthreads();
        if (wid == 0) {
            int s = (lane < 8) ? wsum[lane] : 0;
            #pragma unroll
            for (int o = 1; o < 8; o <<= 1) {
                int y = __shfl_up_sync(0xffffffffu, s, o);
                if (lane >= o) s += y;
            }
            if (lane < 8) wsum[lane] = s;
        }
        __syncthreads();
        int excl = xv - v + (wid > 0 ? wsum[wid - 1] : 0);
        if (i < N) g_rowstart[i] = excl;
        if (tid == 255) g_blocksum[cb] = excl + v;
        __syncthreads();
    }
    gridbar(nb);

    // phase 3: block 0 scans the block sums
    if (bid == 0) {
        int v0 = (tid < nbS) ? g_blocksum[tid] : 0;
        int v1 = (tid + 256 < nbS) ? g_blocksum[tid + 256] : 0;
        sA[tid] = v0; sA[tid + 256] = v1;
        __syncthreads();
        int* src = sA; int* dst = sB;
        for (int o = 1; o < 512; o <<= 1) {
            dst[tid]       = src[tid]       + ((tid >= o)       ? src[tid - o]       : 0);
            dst[tid + 256] = src[tid + 256] + ((tid + 256 >= o) ? src[tid + 256 - o] : 0);
            __syncthreads();
            int* t = src; src = dst; dst = t;
        }
        if (tid < nbS) g_blocksum[tid] = src[tid] - v0;
        if (tid + 256 < nbS) g_blocksum[tid + 256] = src[tid + 256] - v1;
    }
    gridbar(nb);

    // phase 4: fill CSR
    for (long long e0 = ((long long)bid * 256 + tid) * 2; e0 < E;
         e0 += (long long)nb * 512) {
        int4 two = *(const int4*)&g_edge[e0];
        {
            int s = two.x, d = two.y;
            float nrm = g_dinv[s] * g_dinv[d];
            int pos = rowstart(d) + atomicAdd(&g_fill[d], 1);
            g_csr[pos] = make_int2(s, __float_as_int(nrm));
        }
        if (e0 + 1 < E) {
            int s = two.z, d = two.w;
            float nrm = g_dinv[s] * g_dinv[d];
            int pos = rowstart(d) + atomicAdd(&g_fill[d], 1);
            g_csr[pos] = make_int2(s, __float_as_int(nrm));
        }
    }
}

// ---- cp.async helpers ------------------------------------------------------
__device__ __forceinline__ void cpasync16(void* dst, const void* src, int srcbytes) {
    unsigned d = (unsigned)__cvta_generic_to_shared(dst);
    asm volatile("cp.async.ca.shared.global [%0], [%1], 16, %2;"
                 :: "r"(d), "l"(src), "r"(srcbytes));
}
#define CP_COMMIT() asm volatile("cp.async.commit_group;")
#define CP_WAIT1()  asm volatile("cp.async.wait_group 1;")
#define CP_WAIT0()  asm volatile("cp.async.wait_group 0;")

__device__ __forceinline__ void mma_tf32(float4& d, unsigned a0, unsigned a1,
                                         unsigned a2, unsigned a3,
                                         unsigned b0, unsigned b1) {
    asm volatile(
        "mma.sync.aligned.m16n8k8.row.col.f32.tf32.tf32.f32 "
        "{%0,%1,%2,%3},{%4,%5,%6,%7},{%8,%9},{%0,%1,%2,%3};"
        : "+f"(d.x), "+f"(d.y), "+f"(d.z), "+f"(d.w)
        : "r"(a0), "r"(a1), "r"(a2), "r"(a3), "r"(b0), "r"(b1));
}

// ---- k_pool: tf32 TC gemm1, double-buffered cp.async (KC=16) --------------
#define KC 16
__global__ __launch_bounds__(256) void k_pool(const float* __restrict__ x,
                                              const float* __restrict__ W1, int N) {
    __shared__ unsigned Xs[2][128][20];
    __shared__ unsigned Ws[2][KC][72];
    int tid = threadIdx.x;
    int lane = tid & 31, w = tid >> 5;
    int node0 = blockIdx.x * 128;
    int la3 = lane & 3, lg2 = lane >> 2;

    auto load = [&](int kk, int b) {
        #pragma unroll
        for (int j = 0; j < 2; j++) {
            int idx = tid + j * 256;
            int n = idx >> 2, kq = idx & 3;
            int gnode = node0 + n;
            cpasync16(&Xs[b][n][kq * 4],
                      x + (size_t)min(gnode, N - 1) * IN_CH + kk + kq * 4,
                      gnode < N ? 16 : 0);
        }
        {
            int k = tid >> 4, nq = tid & 15;
            cpasync16(&Ws[b][k][nq * 4],
                      W1 + (size_t)k * 64 + (size_t)kk * 64 + nq * 4, 16);
        }
        CP_COMMIT();
    };

    float4 acc[8];
    #pragma unroll
    for (int t = 0; t < 8; t++) acc[t] = make_float4(0.f, 0.f, 0.f, 0.f);

    load(0, 0);
    #pragma unroll
    for (int it = 0; it < IN_CH / KC; it++) {
        int b = it & 1;
        if (it < IN_CH / KC - 1) { load((it + 1) * KC, b ^ 1); CP_WAIT1(); }
        else                     { CP_WAIT0(); }
        __syncthreads();
        #pragma unroll
        for (int ks = 0; ks < KC; ks += 8) {
            int r0 = w * 16 + lg2;
            unsigned a0 = Xs[b][r0][ks + la3];
            unsigned a1 = Xs[b][r0 + 8][ks + la3];
            unsigned a2 = Xs[b][r0][ks + la3 + 4];
            unsigned a3 = Xs[b][r0 + 8][ks + la3 + 4];
            #pragma unroll
            for (int t = 0; t < 8; t++) {
                unsigned b0 = Ws[b][ks + la3][t * 8 + lg2];
                unsigned b1 = Ws[b][ks + la3 + 4][t * 8 + lg2];
                mma_tf32(acc[t], a0, a1, a2, a3, b0, b1);
            }
        }
        __syncthreads();
    }
    int rlo = node0 + w * 16 + lg2;
    int rhi = rlo + 8;
    #pragma unroll
    for (int t = 0; t < 8; t++) {
        int h2idx = t * 4 + la3;
        if (rlo < N) g_h1h[(size_t)rlo * 32 + h2idx] = __floats2half2_rn(acc[t].x, acc[t].y);
        if (rhi < N) g_h1h[(size_t)rhi * 32 + h2idx] = __floats2half2_rn(acc[t].z, acc[t].w);
    }
}

// accumulate 8 fp16 feats (uint4) scaled by n into acc[8]
__device__ __forceinline__ void acc8(float* acc, uint4 u, float n) {
    __half2* h = (__half2*)&u;
    #pragma unroll
    for (int i = 0; i < 4; i++) {
        float2 f = __half22float2(h[i]);
        acc[2 * i]     += f.x * n;
        acc[2 * i + 1] += f.y * n;
    }
}

// ---- k_tail: [gather1+gemm2] -> gridbar -> [gather2+softmax] --------------
__global__ __launch_bounds__(256, 6) void k_tail(const float* __restrict__ b1,
                                                 const float* __restrict__ W2,
                                                 const float* __restrict__ b2,
                                                 float* __restrict__ out, int N) {
    __shared__ float ts[32][68];
    __shared__ float W2t[16][68];
    __shared__ float b1s[64];
    int tid = threadIdx.x;
    unsigned bid = blockIdx.x, nb = gridDim.x;
    for (int i = tid; i < 64 * 16; i += 256) W2t[i & 15][i >> 4] = W2[i];
    if (tid < 64) b1s[tid] = b1[tid];
    __syncthreads();

    // ---- phase 1: gather1 + gemm2, 32 nodes/tile, 8 thr/node ----
    int nTiles = (N + 31) / 32;
    int li = tid >> 3, c = tid & 7;
    for (int tile = bid; tile < nTiles; tile += nb) {
        int node = tile * 32 + li;
        bool valid = node < N;
        int cn = valid ? node : N - 1;   // clamp

        const uint4* selfrow = (const uint4*)(g_h1h + (size_t)cn * 32);
        float di = g_dinv[cn];
        float sc = di * di;
        float acc[8] = {0, 0, 0, 0, 0, 0, 0, 0};
        acc8(acc, selfrow[c], sc);

        int e = rowstart(cn);
        int deg = g_incnt[cn];
        int dmax = deg;
        dmax = max(dmax, __shfl_xor_sync(0xffffffffu, dmax, 8));
        dmax = max(dmax, __shfl_xor_sync(0xffffffffu, dmax, 16));

        for (int base = 0; base < dmax; base += 8) {
            int off = base + c;
            int cl = (deg > 0) ? (e + min(off, deg - 1)) : 0;
            int2 ce = g_csr[cl];
            #pragma unroll
            for (int j = 0; j < 8; j++) {
                int  srcn = __shfl_sync(0xffffffffu, ce.x, j, 8);
                int  nrmb = __shfl_sync(0xffffffffu, ce.y, j, 8);
                uint4 v = ((const uint4*)(g_h1h + (size_t)srcn * 32))[c];
                if (base + j < deg) acc8(acc, v, __int_as_float(nrmb));
            }
        }
        #pragma unroll
        for (int i = 0; i < 8; i++)
            acc[i] = fmaxf(acc[i] + b1s[c * 8 + i], 0.f);
        *(float4*)&ts[li][c * 8]     = make_float4(acc[0], acc[1], acc[2], acc[3]);
        *(float4*)&ts[li][c * 8 + 4] = make_float4(acc[4], acc[5], acc[6], acc[7]);
        __syncthreads();

        // gemm2: thread computes feats (2fp, 2fp+1) of node n2, stores half2
        int n2 = tid >> 3, fp = tid & 7;
        float a0 = 0.f, a1 = 0.f;
        #pragma unroll
        for (int k = 0; k < 64; k += 4) {
            float4 t  = *(const float4*)&ts[n2][k];
            float4 w0 = *(const float4*)&W2t[2 * fp][k];
            float4 w1 = *(const float4*)&W2t[2 * fp + 1][k];
            a0 += t.x * w0.x + t.y * w0.y + t.z * w0.z + t.w * w0.w;
            a1 += t.x * w1.x + t.y * w1.y + t.z * w1.z + t.w * w1.w;
        }
        int gnode = tile * 32 + n2;
        if (gnode < N) g_h2h[(size_t)gnode * 8 + fp] = __floats2half2_rn(a0, a1);
        __syncthreads();   // ts reused next tile
    }
    gridbar(nb);

    // ---- phase 2: gather2 + bias + log_softmax, 64 nodes/chunk, 4 thr/node
    int nChunks = (N + 63) / 64;
    int li2 = tid >> 2, c2 = tid & 3;
    for (int ch = bid; ch < nChunks; ch += nb) {
        int node = ch * 64 + li2;
        bool valid = node < N;
        int cn = valid ? node : N - 1;

        float di = g_dinv[cn];
        float sc = di * di;
        uint2 su = ((const uint2*)(g_h2h + (size_t)cn * 8))[c2];
        float2 s0 = __half22float2(*(__half2*)&su.x);
        float2 s1 = __half22float2(*(__half2*)&su.y);
        float4 acc = make_float4(s0.x * sc, s0.y * sc, s1.x * sc, s1.y * sc);

        int e = rowstart(cn);
        int deg = g_incnt[cn];
        if (valid && c2 == 0) { g_incnt[cn] = 0; g_fill[cn] = 0; }  // zero for next call
        int dmax = deg;
        dmax = max(dmax, __shfl_xor_sync(0xffffffffu, dmax, 4));
        dmax = max(dmax, __shfl_xor_sync(0xffffffffu, dmax, 8));
        dmax = max(dmax, __shfl_xor_sync(0xffffffffu, dmax, 16));

        for (int base = 0; base < dmax; base += 4) {
            int off = base + c2;
            int cl = (deg > 0) ? (e + min(off, deg - 1)) : 0;
            int2 ce = g_csr[cl];
            #pragma unroll
            for (int j = 0; j < 4; j++) {
                int srcn = __shfl_sync(0xffffffffu, ce.x, j, 4);
                int nrmb = __shfl_sync(0xffffffffu, ce.y, j, 4);
                uint2 vu = ((const uint2*)(g_h2h + (size_t)srcn * 8))[c2];
                if (base + j < deg) {
                    float nn = __int_as_float(nrmb);
                    float2 f0 = __half22float2(*(__half2*)&vu.x);
                    float2 f1 = __half22float2(*(__half2*)&vu.y);
                    acc.x += f0.x * nn; acc.y += f0.y * nn;
                    acc.z += f1.x * nn; acc.w += f1.y * nn;
                }
            }
        }
        float4 b = ((const float4*)b2)[c2];
        acc.x += b.x; acc.y += b.y; acc.z += b.z; acc.w += b.w;
        float m = fmaxf(fmaxf(acc.x, acc.y), fmaxf(acc.z, acc.w));
        m = fmaxf(m, __shfl_xor_sync(0xffffffffu, m, 1));
        m = fmaxf(m, __shfl_xor_sync(0xffffffffu, m, 2));
        float se = expf(acc.x - m) + expf(acc.y - m) + expf(acc.z - m) + expf(acc.w - m);
        se += __shfl_xor_sync(0xffffffffu, se, 1);
        se += __shfl_xor_sync(0xffffffffu, se, 2);
        float l = m + logf(se);
        acc.x -= l; acc.y -= l; acc.z -= l; acc.w -= l;
        if (valid) ((float4*)(out + (size_t)node * OUT_CH))[c2] = acc;
    }
}

// ---------------------------------------------------------------------------
extern "C" void kernel_launch(void* const* d_in, const int* in_sizes, int n_in,
                              void* d_out, int out_size) {
    const float* x  = (const float*)d_in[0];
    const void*  ei = d_in[1];
    const float* W1 = (const float*)d_in[2];
    const float* b1 = (const float*)d_in[3];
    const float* W2 = (const float*)d_in[4];
    const float* b2 = (const float*)d_in[5];
    float* out = (float*)d_out;

    int N = in_sizes[0] / IN_CH;
    long long E = in_sizes[1] / 2;

    int nwords = (int)((E < 512) ? E : 512);
    int nbS = (N + 255) / 256;
    int nbG = (N + 127) / 128;

    int sms = 148;
    cudaDeviceGetAttribute(&sms, cudaDevAttrMultiProcessorCount, 0);
    int nbar = sms * 6;   // __launch_bounds__(256,6) guarantees co-residency

    k_edges<<<nbar, 256>>>(ei, N, E, nwords, nbS);
    k_pool<<<nbG, 256>>>(x, W1, N);
    k_tail<<<nbar, 256>>>(b1, W2, b2, out, N);
}

// round 15
// speedup vs baseline: 1.0679x; 1.0679x over previous
#include <cuda_runtime.h>
#include <cuda_fp16.h>

// ---------------------------------------------------------------------------
// GCN 2-layer, round 15: 4 launches.
//   k_edges : prep(+slot assign)+scan+sums+fill(no atomics) via grid barriers
//   k_pool  : tf32 TC gemm1, cp.async double-buffered (KC=16)
//   k_g1g2  : gather1+gemm2 (fp16 h1 in, fp16 h2 out), shuffle-distributed
//   k_gather2: gather2+softmax on fp16 h2, counter-zero tail
// ---------------------------------------------------------------------------

#define MAXN 131072
#define MAXE 4194304
#define IN_CH 256
#define HID 64
#define OUT_CH 16

__device__ __half2 g_h1h[(size_t)MAXN * 32];   // h1 fp16, 128B per row
__device__ __half2 g_h2h[(size_t)MAXN * 8];    // h2 fp16, 32B per row
__device__ float g_dinv[MAXN];
__device__ int   g_incnt[MAXN];      // zero at entry (static init / gather2 tail)
__device__ int   g_rowstart[MAXN];
__device__ int   g_blocksum[1024];
__device__ int2  g_edge[MAXE];
__device__ int   g_pos[MAXE];        // within-row slot, assigned in phase 1
__device__ int2  g_csr[MAXE];        // (src, norm-bits) grouped by dst
__device__ unsigned g_barcnt;        // grid barrier arrive count (self-resetting)
__device__ volatile unsigned g_bargen;  // generation (monotonic)

__device__ __forceinline__ int rowstart(int i) {
    return g_rowstart[i] + g_blocksum[i >> 8];
}

__device__ __forceinline__ void gridbar(unsigned nb) {
    __syncthreads();
    if (threadIdx.x == 0) {
        __threadfence();
        unsigned gen = g_bargen;
        unsigned t = atomicAdd(&g_barcnt, 1u);
        if (t == nb - 1) {
            g_barcnt = 0;
            __threadfence();
            g_bargen = gen + 1;
        } else {
            while (g_bargen == gen) __nanosleep(40);
        }
        __threadfence();
    }
    __syncthreads();
}

// ---- k_edges: prep(+slots) + scan + sums-scan + atomic-free fill ----------
__global__ __launch_bounds__(256, 6) void k_edges(const void* __restrict__ ei,
                                                  int N, long long E,
                                                  int nwords, int nbS) {
    __shared__ int s_is64;
    __shared__ int wsum[8];
    __shared__ int sA[512], sB[512];
    int tid = threadIdx.x;
    unsigned bid = blockIdx.x, nb = gridDim.x;
    int lane = tid & 31, wid = tid >> 5;

    {
        const long long* p = (const long long*)ei;
        int ok = 1;
        #pragma unroll
        for (int j = 0; j < 2; j++) {
            int wd = tid + j * 256;
            if (wd < nwords) {
                long long v = __ldg(p + wd);
                if (v < 0 || v >= (long long)N) ok = 0;
            }
        }
        int all = __syncthreads_and(ok);
        if (tid == 0) s_is64 = all;
    }
    __syncthreads();
    int is64 = s_is64;

    // phase 1: decode edges + in-degree; atomic return value = CSR slot
    for (long long e = (long long)bid * 256 + tid; e < E; e += (long long)nb * 256) {
        int s, d;
        if (is64) {
            s = (int)__ldg(((const long long*)ei) + e);
            d = (int)__ldg(((const long long*)ei) + E + e);
        } else {
            s = __ldg(((const int*)ei) + e);
            d = __ldg(((const int*)ei) + E + e);
        }
        g_edge[e] = make_int2(s, d);
        g_pos[e] = atomicAdd(&g_incnt[d], 1);
    }
    gridbar(nb);

    // phase 2: per-256-chunk scans + dinv
    for (int cb = bid; cb < nbS; cb += nb) {
        int i = cb * 256 + tid;
        int v = (i < N) ? g_incnt[i] : 0;
        if (i < N) g_dinv[i] = rsqrtf((float)(v + 1));   // +1 self-loop
        int xv = v;
        #pragma unroll
        for (int o = 1; o < 32; o <<= 1) {
            int y = __shfl_up_sync(0xffffffffu, xv, o);
            if (lane >= o) xv += y;
        }
        if (lane == 31) wsum[wid] = xv;
        __syncthreads();
        if (wid == 0) {
            int s = (lane < 8) ? wsum[lane] : 0;
            #pragma unroll
            for (int o = 1; o < 8; o <<= 1) {
                int y = __shfl_up_sync(0xffffffffu, s, o);
                if (lane >= o) s += y;
            }
            if (lane < 8) wsum[lane] = s;
        }
        __syncthreads();
        int excl = xv - v + (wid > 0 ? wsum[wid - 1] : 0);
        if (i < N) g_rowstart[i] = excl;
        if (tid == 255) g_blocksum[cb] = excl + v;
        __syncthreads();
    }
    gridbar(nb);

    // phase 3: block 0 exclusive-scans the <=512 block sums
    if (bid == 0) {
        int v0 = (tid < nbS) ? g_blocksum[tid] : 0;
        int v1 = (tid + 256 < nbS) ? g_blocksum[tid + 256] : 0;
        sA[tid] = v0; sA[tid + 256] = v1;
        __syncthreads();
        int* src = sA; int* dst = sB;
        for (int o = 1; o < 512; o <<= 1) {
            dst[tid]       = src[tid]       + ((tid >= o)       ? src[tid - o]       : 0);
            dst[tid + 256] = src[tid + 256] + ((tid + 256 >= o) ? src[tid + 256 - o] : 0);
            __syncthreads();
            int* t = src; src = dst; dst = t;
        }
        if (tid < nbS) g_blocksum[tid] = src[tid] - v0;
        if (tid + 256 < nbS) g_blocksum[tid + 256] = src[tid + 256] - v1;
    }
    gridbar(nb);

    // phase 4: fill CSR — NO atomics, independent iterations (2 int4 loads)
    for (long long e0 = ((long long)bid * 256 + tid) * 2; e0 < E;
         e0 += (long long)nb * 512) {
        int4 two = *(const int4*)&g_edge[e0];
        int2 pp  = *(const int2*)&g_pos[e0];
        {
            int s = two.x, d = two.y;
            float nrm = g_dinv[s] * g_dinv[d];
            g_csr[rowstart(d) + pp.x] = make_int2(s, __float_as_int(nrm));
        }
        if (e0 + 1 < E) {
            int s = two.z, d = two.w;
            float nrm = g_dinv[s] * g_dinv[d];
            g_csr[rowstart(d) + pp.y] = make_int2(s, __float_as_int(nrm));
        }
    }
}

// ---- cp.async helpers ------------------------------------------------------
__device__ __forceinline__ void cpasync16(void* dst, const void* src, int srcbytes) {
    unsigned d = (unsigned)__cvta_generic_to_shared(dst);
    asm volatile("cp.async.ca.shared.global [%0], [%1], 16, %2;"
                 :: "r"(d), "l"(src), "r"(srcbytes));
}
#define CP_COMMIT() asm volatile("cp.async.commit_group;")
#define CP_WAIT1()  asm volatile("cp.async.wait_group 1;")
#define CP_WAIT0()  asm volatile("cp.async.wait_group 0;")

__device__ __forceinline__ void mma_tf32(float4& d, unsigned a0, unsigned a1,
                                         unsigned a2, unsigned a3,
                                         unsigned b0, unsigned b1) {
    asm volatile(
        "mma.sync.aligned.m16n8k8.row.col.f32.tf32.tf32.f32 "
        "{%0,%1,%2,%3},{%4,%5,%6,%7},{%8,%9},{%0,%1,%2,%3};"
        : "+f"(d.x), "+f"(d.y), "+f"(d.z), "+f"(d.w)
        : "r"(a0), "r"(a1), "r"(a2), "r"(a3), "r"(b0), "r"(b1));
}

// ---- k_pool: tf32 TC gemm1, double-buffered cp.async (KC=16) --------------
#define KC 16
__global__ __launch_bounds__(256) void k_pool(const float* __restrict__ x,
                                              const float* __restrict__ W1, int N) {
    __shared__ unsigned Xs[2][128][20];
    __shared__ unsigned Ws[2][KC][72];
    int tid = threadIdx.x;
    int lane = tid & 31, w = tid >> 5;
    int node0 = blockIdx.x * 128;
    int la3 = lane & 3, lg2 = lane >> 2;

    auto load = [&](int kk, int b) {
        #pragma unroll
        for (int j = 0; j < 2; j++) {
            int idx = tid + j * 256;
            int n = idx >> 2, kq = idx & 3;
            int gnode = node0 + n;
            cpasync16(&Xs[b][n][kq * 4],
                      x + (size_t)min(gnode, N - 1) * IN_CH + kk + kq * 4,
                      gnode < N ? 16 : 0);
        }
        {
            int k = tid >> 4, nq = tid & 15;
            cpasync16(&Ws[b][k][nq * 4],
                      W1 + (size_t)k * 64 + (size_t)kk * 64 + nq * 4, 16);
        }
        CP_COMMIT();
    };

    float4 acc[8];
    #pragma unroll
    for (int t = 0; t < 8; t++) acc[t] = make_float4(0.f, 0.f, 0.f, 0.f);

    load(0, 0);
    #pragma unroll
    for (int it = 0; it < IN_CH / KC; it++) {
        int b = it & 1;
        if (it < IN_CH / KC - 1) { load((it + 1) * KC, b ^ 1); CP_WAIT1(); }
        else                     { CP_WAIT0(); }
        __syncthreads();
        #pragma unroll
        for (int ks = 0; ks < KC; ks += 8) {
            int r0 = w * 16 + lg2;
            unsigned a0 = Xs[b][r0][ks + la3];
            unsigned a1 = Xs[b][r0 + 8][ks + la3];
            unsigned a2 = Xs[b][r0][ks + la3 + 4];
            unsigned a3 = Xs[b][r0 + 8][ks + la3 + 4];
            #pragma unroll
            for (int t = 0; t < 8; t++) {
                unsigned b0 = Ws[b][ks + la3][t * 8 + lg2];
                unsigned b1 = Ws[b][ks + la3 + 4][t * 8 + lg2];
                mma_tf32(acc[t], a0, a1, a2, a3, b0, b1);
            }
        }
        __syncthreads();
    }
    int rlo = node0 + w * 16 + lg2;
    int rhi = rlo + 8;
    #pragma unroll
    for (int t = 0; t < 8; t++) {
        int h2idx = t * 4 + la3;
        if (rlo < N) g_h1h[(size_t)rlo * 32 + h2idx] = __floats2half2_rn(acc[t].x, acc[t].y);
        if (rhi < N) g_h1h[(size_t)rhi * 32 + h2idx] = __floats2half2_rn(acc[t].z, acc[t].w);
    }
}

// accumulate 8 fp16 feats (uint4) scaled by n into acc[8]
__device__ __forceinline__ void acc8(float* acc, uint4 u, float n) {
    __half2* h = (__half2*)&u;
    #pragma unroll
    for (int i = 0; i < 4; i++) {
        float2 f = __half22float2(h[i]);
        acc[2 * i]     += f.x * n;
        acc[2 * i + 1] += f.y * n;
    }
}

// ---- k_g1g2: gather1 + gemm2, 32 nodes/block, 8 thr/node; h2 -> fp16 ------
__global__ __launch_bounds__(256) void k_g1g2(const float* __restrict__ b1,
                                              const float* __restrict__ W2, int N) {
    __shared__ float ts[32][68];
    __shared__ float W2t[16][68];
    __shared__ float b1s[64];
    int tid = threadIdx.x;
    for (int i = tid; i < 64 * 16; i += 256) W2t[i & 15][i >> 4] = W2[i];
    if (tid < 64) b1s[tid] = b1[tid];

    int li = tid >> 3, c = tid & 7;
    int node = blockIdx.x * 32 + li;
    bool valid = node < N;
    if (!valid) node = N - 1;   // clamp: redundant-but-valid

    const uint4* selfrow = (const uint4*)(g_h1h + (size_t)node * 32);
    float di = g_dinv[node];
    float sc = di * di;
    float acc[8] = {0, 0, 0, 0, 0, 0, 0, 0};
    acc8(acc, selfrow[c], sc);

    int e = rowstart(node);
    int deg = g_incnt[node];
    int dmax = deg;
    dmax = max(dmax, __shfl_xor_sync(0xffffffffu, dmax, 8));
    dmax = max(dmax, __shfl_xor_sync(0xffffffffu, dmax, 16));

    for (int base = 0; base < dmax; base += 8) {
        int off = base + c;
        int cl = (deg > 0) ? (e + min(off, deg - 1)) : 0;   // clamped, valid
        int2 ce = g_csr[cl];
        #pragma unroll
        for (int j = 0; j < 8; j++) {
            int  srcn = __shfl_sync(0xffffffffu, ce.x, j, 8);
            int  nrmb = __shfl_sync(0xffffffffu, ce.y, j, 8);
            uint4 v = ((const uint4*)(g_h1h + (size_t)srcn * 32))[c];
            if (base + j < deg) acc8(acc, v, __int_as_float(nrmb));
        }
    }
    #pragma unroll
    for (int i = 0; i < 8; i++)
        acc[i] = fmaxf(acc[i] + b1s[c * 8 + i], 0.f);
    *(float4*)&ts[li][c * 8]     = make_float4(acc[0], acc[1], acc[2], acc[3]);
    *(float4*)&ts[li][c * 8 + 4] = make_float4(acc[4], acc[5], acc[6], acc[7]);
    __syncthreads();

    // gemm2: thread computes feats (2fp, 2fp+1) of node n2; one half2 store
    int n2 = tid >> 3, fp = tid & 7;
    float a0 = 0.f, a1 = 0.f;
    #pragma unroll
    for (int k = 0; k < 64; k += 4) {
        float4 t  = *(const float4*)&ts[n2][k];
        float4 w0 = *(const float4*)&W2t[2 * fp][k];
        float4 w1 = *(const float4*)&W2t[2 * fp + 1][k];
        a0 += t.x * w0.x + t.y * w0.y + t.z * w0.z + t.w * w0.w;
        a1 += t.x * w1.x + t.y * w1.y + t.z * w1.z + t.w * w1.w;
    }
    int gnode = blockIdx.x * 32 + n2;
    if (gnode < N) g_h2h[(size_t)gnode * 8 + fp] = __floats2half2_rn(a0, a1);
}

// ---- k_gather2: gather2 + bias + log_softmax on fp16 h2; zero tail --------
__global__ __launch_bounds__(256) void k_gather2(float* __restrict__ out,
                                                 const float* __restrict__ b2, int N) {
    int tid = threadIdx.x;
    int li = tid >> 2, c2 = tid & 3;
    int node = blockIdx.x * 64 + li;
    bool valid = node < N;
    if (!valid) node = N - 1;

    float di = g_dinv[node];
    float sc = di * di;
    uint2 su = ((const uint2*)(g_h2h + (size_t)node * 8))[c2];
    float2 s0 = __half22float2(*(__half2*)&su.x);
    float2 s1 = __half22float2(*(__half2*)&su.y);
    float4 acc = make_float4(s0.x * sc, s0.y * sc, s1.x * sc, s1.y * sc);

    int e = rowstart(node);
    int deg = g_incnt[node];
    if (valid && c2 == 0) g_incnt[node] = 0;   // zero for next call (after read)
    int dmax = deg;
    dmax = max(dmax, __shfl_xor_sync(0xffffffffu, dmax, 4));
    dmax = max(dmax, __shfl_xor_sync(0xffffffffu, dmax, 8));
    dmax = max(dmax, __shfl_xor_sync(0xffffffffu, dmax, 16));

    for (int base = 0; base < dmax; base += 4) {
        int off = base + c2;
        int cl = (deg > 0) ? (e + min(off, deg - 1)) : 0;
        int2 ce = g_csr[cl];
        #pragma unroll
        for (int j = 0; j < 4; j++) {
            int srcn = __shfl_sync(0xffffffffu, ce.x, j, 4);
            int nrmb = __shfl_sync(0xffffffffu, ce.y, j, 4);
            uint2 vu = ((const uint2*)(g_h2h + (size_t)srcn * 8))[c2];
            if (base + j < deg) {
                float nn = __int_as_float(nrmb);
                float2 f0 = __half22float2(*(__half2*)&vu.x);
                float2 f1 = __half22float2(*(__half2*)&vu.y);
                acc.x += f0.x * nn; acc.y += f0.y * nn;
                acc.z += f1.x * nn; acc.w += f1.y * nn;
            }
        }
    }
    float4 b = ((const float4*)b2)[c2];
    acc.x += b.x; acc.y += b.y; acc.z += b.z; acc.w += b.w;
    float m = fmaxf(fmaxf(acc.x, acc.y), fmaxf(acc.z, acc.w));
    m = fmaxf(m, __shfl_xor_sync(0xffffffffu, m, 1));
    m = fmaxf(m, __shfl_xor_sync(0xffffffffu, m, 2));
    float se = expf(acc.x - m) + expf(acc.y - m) + expf(acc.z - m) + expf(acc.w - m);
    se += __shfl_xor_sync(0xffffffffu, se, 1);
    se += __shfl_xor_sync(0xffffffffu, se, 2);
    float l = m + logf(se);
    acc.x -= l; acc.y -= l; acc.z -= l; acc.w -= l;
    if (valid) ((float4*)(out + (size_t)node * OUT_CH))[c2] = acc;
}

// ---------------------------------------------------------------------------
extern "C" void kernel_launch(void* const* d_in, const int* in_sizes, int n_in,
                              void* d_out, int out_size) {
    const float* x  = (const float*)d_in[0];
    const void*  ei = d_in[1];
    const float* W1 = (const float*)d_in[2];
    const float* b1 = (const float*)d_in[3];
    const float* W2 = (const float*)d_in[4];
    const float* b2 = (const float*)d_in[5];
    float* out = (float*)d_out;

    int N = in_sizes[0] / IN_CH;
    long long E = in_sizes[1] / 2;

    int nwords = (int)((E < 512) ? E : 512);
    int nbS = (N + 255) / 256;
    int nbG = (N + 127) / 128;

    int sms = 148;
    cudaDeviceGetAttribute(&sms, cudaDevAttrMultiProcessorCount, 0);
    int nbar = sms * 6;   // __launch_bounds__(256,6) guarantees co-residency

    k_edges<<<nbar, 256>>>(ei, N, E, nwords, nbS);
    k_pool<<<nbG, 256>>>(x, W1, N);
    k_g1g2<<<(N + 31) / 32, 256>>>(b1, W2, N);
    k_gather2<<<(N + 63) / 64, 256>>>(out, b2, N);
}

// round 16
// speedup vs baseline: 1.1460x; 1.0731x over previous
#include <cuda_runtime.h>
#include <cuda_fp16.h>

// ---------------------------------------------------------------------------
// GCN 2-layer, round 16: 4 launches.
//   k_pool  : tf32 TC gemm1 (cp.async double-buffered) || edge-decode+degree
//   k_fin   : scan + sums + atomic-free CSR fill (grid-barrier fused)
//   k_g1g2  : gather1+gemm2 (fp16 h1 in, fp16 h2 out), shuffle-distributed
//   k_gather2: gather2+softmax on fp16 h2, counter-zero tail
// ---------------------------------------------------------------------------

#define MAXN 131072
#define MAXE 4194304
#define IN_CH 256
#define HID 64
#define OUT_CH 16
#define PREP_CHUNK 8192

__device__ __half2 g_h1h[(size_t)MAXN * 32];   // h1 fp16, 128B per row
__device__ __half2 g_h2h[(size_t)MAXN * 8];    // h2 fp16, 32B per row
__device__ float g_dinv[MAXN];
__device__ int   g_incnt[MAXN];      // zero at entry (static init / gather2 tail)
__device__ int   g_rowstart[MAXN];
__device__ int   g_blocksum[1024];
__device__ int2  g_edge[MAXE];
__device__ int   g_pos[MAXE];        // within-row slot, from degree atomic
__device__ int2  g_csr[MAXE];        // (src, norm-bits) grouped by dst
__device__ unsigned g_barcnt;        // grid barrier arrive count (self-resetting)
__device__ volatile unsigned g_bargen;  // generation (monotonic)

__device__ __forceinline__ int rowstart(int i) {
    return g_rowstart[i] + g_blocksum[i >> 8];
}

__device__ __forceinline__ void gridbar(unsigned nb) {
    __syncthreads();
    if (threadIdx.x == 0) {
        __threadfence();
        unsigned gen = g_bargen;
        unsigned t = atomicAdd(&g_barcnt, 1u);
        if (t == nb - 1) {
            g_barcnt = 0;
            __threadfence();
            g_bargen = gen + 1;
        } else {
            while (g_bargen == gen) __nanosleep(40);
        }
        __threadfence();
    }
    __syncthreads();
}

// ---- cp.async helpers ------------------------------------------------------
__device__ __forceinline__ void cpasync16(void* dst, const void* src, int srcbytes) {
    unsigned d = (unsigned)__cvta_generic_to_shared(dst);
    asm volatile("cp.async.ca.shared.global [%0], [%1], 16, %2;"
                 :: "r"(d), "l"(src), "r"(srcbytes));
}
#define CP_COMMIT() asm volatile("cp.async.commit_group;")
#define CP_WAIT1()  asm volatile("cp.async.wait_group 1;")
#define CP_WAIT0()  asm volatile("cp.async.wait_group 0;")

__device__ __forceinline__ void mma_tf32(float4& d, unsigned a0, unsigned a1,
                                         unsigned a2, unsigned a3,
                                         unsigned b0, unsigned b1) {
    asm volatile(
        "mma.sync.aligned.m16n8k8.row.col.f32.tf32.tf32.f32 "
        "{%0,%1,%2,%3},{%4,%5,%6,%7},{%8,%9},{%0,%1,%2,%3};"
        : "+f"(d.x), "+f"(d.y), "+f"(d.z), "+f"(d.w)
        : "r"(a0), "r"(a1), "r"(a2), "r"(a3), "r"(b0), "r"(b1));
}

// ---- k_pool: gemm1 tiles || prep chunks (decode + degree atomic) ----------
// Ticket q%4==3 (while chunks remain) -> prep chunk; else gemm tile.
#define KC 16
__global__ __launch_bounds__(256) void k_pool(const float* __restrict__ x,
                                              const void* __restrict__ ei,
                                              const float* __restrict__ W1,
                                              int N, long long E,
                                              int nbG, int nchunks, int nwords) {
    __shared__ unsigned Xs[2][128][20];
    __shared__ unsigned Ws[2][KC][72];
    int tid = threadIdx.x;
    int q = blockIdx.x;
    int lane = tid & 31, w = tid >> 5;

    bool isprep = ((q & 3) == 3) && ((q >> 2) < nchunks);
    if (isprep) {
        // per-block dtype probe (L2-cached)
        const long long* p = (const long long*)ei;
        int ok = 1;
        #pragma unroll
        for (int j = 0; j < 2; j++) {
            int wd = tid + j * 256;
            if (wd < nwords) {
                long long v = __ldg(p + wd);
                if (v < 0 || v >= (long long)N) ok = 0;
            }
        }
        int is64 = __syncthreads_and(ok);
        long long s0 = (long long)(q >> 2) * PREP_CHUNK;
        long long s1 = s0 + PREP_CHUNK; if (s1 > E) s1 = E;
        if (is64) {
            const long long* pp = (const long long*)ei;
            for (long long e = s0 + tid; e < s1; e += 256) {
                int s = (int)__ldg(pp + e);
                int d = (int)__ldg(pp + E + e);
                g_edge[e] = make_int2(s, d);
                g_pos[e] = atomicAdd(&g_incnt[d], 1);
            }
        } else {
            const int* pp = (const int*)ei;
            for (long long e = s0 + tid; e < s1; e += 256) {
                int s = __ldg(pp + e);
                int d = __ldg(pp + E + e);
                g_edge[e] = make_int2(s, d);
                g_pos[e] = atomicAdd(&g_incnt[d], 1);
            }
        }
        return;
    }

    int g = q - min(q >> 2, nchunks);
    if (g >= nbG) return;

    int node0 = g * 128;
    int la3 = lane & 3, lg2 = lane >> 2;

    auto load = [&](int kk, int b) {
        #pragma unroll
        for (int j = 0; j < 2; j++) {
            int idx = tid + j * 256;
            int n = idx >> 2, kq = idx & 3;
            int gnode = node0 + n;
            cpasync16(&Xs[b][n][kq * 4],
                      x + (size_t)min(gnode, N - 1) * IN_CH + kk + kq * 4,
                      gnode < N ? 16 : 0);
        }
        {
            int k = tid >> 4, nq = tid & 15;
            cpasync16(&Ws[b][k][nq * 4],
                      W1 + (size_t)k * 64 + (size_t)kk * 64 + nq * 4, 16);
        }
        CP_COMMIT();
    };

    float4 acc[8];
    #pragma unroll
    for (int t = 0; t < 8; t++) acc[t] = make_float4(0.f, 0.f, 0.f, 0.f);

    load(0, 0);
    #pragma unroll
    for (int it = 0; it < IN_CH / KC; it++) {
        int b = it & 1;
        if (it < IN_CH / KC - 1) { load((it + 1) * KC, b ^ 1); CP_WAIT1(); }
        else                     { CP_WAIT0(); }
        __syncthreads();
        #pragma unroll
        for (int ks = 0; ks < KC; ks += 8) {
            int r0 = w * 16 + lg2;
            unsigned a0 = Xs[b][r0][ks + la3];
            unsigned a1 = Xs[b][r0 + 8][ks + la3];
            unsigned a2 = Xs[b][r0][ks + la3 + 4];
            unsigned a3 = Xs[b][r0 + 8][ks + la3 + 4];
            #pragma unroll
            for (int t = 0; t < 8; t++) {
                unsigned b0 = Ws[b][ks + la3][t * 8 + lg2];
                unsigned b1 = Ws[b][ks + la3 + 4][t * 8 + lg2];
                mma_tf32(acc[t], a0, a1, a2, a3, b0, b1);
            }
        }
        __syncthreads();
    }
    int rlo = node0 + w * 16 + lg2;
    int rhi = rlo + 8;
    #pragma unroll
    for (int t = 0; t < 8; t++) {
        int h2idx = t * 4 + la3;
        if (rlo < N) g_h1h[(size_t)rlo * 32 + h2idx] = __floats2half2_rn(acc[t].x, acc[t].y);
        if (rhi < N) g_h1h[(size_t)rhi * 32 + h2idx] = __floats2half2_rn(acc[t].z, acc[t].w);
    }
}

// ---- k_fin: scan + sums-scan + atomic-free fill (grid-barrier fused) ------
__global__ __launch_bounds__(256, 6) void k_fin(int N, long long E, int nbS) {
    __shared__ int wsum[8];
    __shared__ int sA[512], sB[512];
    int tid = threadIdx.x;
    unsigned bid = blockIdx.x, nb = gridDim.x;
    int lane = tid & 31, wid = tid >> 5;

    // phase A: per-256-chunk scans + dinv
    for (int cb = bid; cb < nbS; cb += nb) {
        int i = cb * 256 + tid;
        int v = (i < N) ? g_incnt[i] : 0;
        if (i < N) g_dinv[i] = rsqrtf((float)(v + 1));   // +1 self-loop
        int xv = v;
        #pragma unroll
        for (int o = 1; o < 32; o <<= 1) {
            int y = __shfl_up_sync(0xffffffffu, xv, o);
            if (lane >= o) xv += y;
        }
        if (lane == 31) wsum[wid] = xv;
        __syncthreads();
        if (wid == 0) {
            int s = (lane < 8) ? wsum[lane] : 0;
            #pragma unroll
            for (int o = 1; o < 8; o <<= 1) {
                int y = __shfl_up_sync(0xffffffffu, s, o);
                if (lane >= o) s += y;
            }
            if (lane < 8) wsum[lane] = s;
        }
        __syncthreads();
        int excl = xv - v + (wid > 0 ? wsum[wid - 1] : 0);
        if (i < N) g_rowstart[i] = excl;
        if (tid == 255) g_blocksum[cb] = excl + v;
        __syncthreads();
    }
    gridbar(nb);

    // phase B: block 0 exclusive-scans the <=512 block sums
    if (bid == 0) {
        int v0 = (tid < nbS) ? g_blocksum[tid] : 0;
        int v1 = (tid + 256 < nbS) ? g_blocksum[tid + 256] : 0;
        sA[tid] = v0; sA[tid + 256] = v1;
        __syncthreads();
        int* src = sA; int* dst = sB;
        for (int o = 1; o < 512; o <<= 1) {
            dst[tid]       = src[tid]       + ((tid >= o)       ? src[tid - o]       : 0);
            dst[tid + 256] = src[tid + 256] + ((tid + 256 >= o) ? src[tid + 256 - o] : 0);
            __syncthreads();
            int* t = src; src = dst; dst = t;
        }
        if (tid < nbS) g_blocksum[tid] = src[tid] - v0;
        if (tid + 256 < nbS) g_blocksum[tid + 256] = src[tid + 256] - v1;
    }
    gridbar(nb);

    // phase C: fill CSR — no atomics, independent iterations
    for (long long e0 = ((long long)bid * 256 + tid) * 2; e0 < E;
         e0 += (long long)nb * 512) {
        int4 two = *(const int4*)&g_edge[e0];
        int2 pp  = *(const int2*)&g_pos[e0];
        {
            int s = two.x, d = two.y;
            float nrm = g_dinv[s] * g_dinv[d];
            g_csr[rowstart(d) + pp.x] = make_int2(s, __float_as_int(nrm));
        }
        if (e0 + 1 < E) {
            int s = two.z, d = two.w;
            float nrm = g_dinv[s] * g_dinv[d];
            g_csr[rowstart(d) + pp.y] = make_int2(s, __float_as_int(nrm));
        }
    }
}

// accumulate 8 fp16 feats (uint4) scaled by n into acc[8]
__device__ __forceinline__ void acc8(float* acc, uint4 u, float n) {
    __half2* h = (__half2*)&u;
    #pragma unroll
    for (int i = 0; i < 4; i++) {
        float2 f = __half22float2(h[i]);
        acc[2 * i]     += f.x * n;
        acc[2 * i + 1] += f.y * n;
    }
}

// ---- k_g1g2: gather1 + gemm2, 32 nodes/block, 8 thr/node; h2 -> fp16 ------
__global__ __launch_bounds__(256) void k_g1g2(const float* __restrict__ b1,
                                              const float* __restrict__ W2, int N) {
    __shared__ float ts[32][68];
    __shared__ float W2t[16][68];
    __shared__ float b1s[64];
    int tid = threadIdx.x;
    for (int i = tid; i < 64 * 16; i += 256) W2t[i & 15][i >> 4] = W2[i];
    if (tid < 64) b1s[tid] = b1[tid];

    int li = tid >> 3, c = tid & 7;
    int node = blockIdx.x * 32 + li;
    bool valid = node < N;
    if (!valid) node = N - 1;   // clamp: redundant-but-valid

    const uint4* selfrow = (const uint4*)(g_h1h + (size_t)node * 32);
    float di = g_dinv[node];
    float sc = di * di;
    float acc[8] = {0, 0, 0, 0, 0, 0, 0, 0};
    acc8(acc, selfrow[c], sc);

    int e = rowstart(node);
    int deg = g_incnt[node];
    int dmax = deg;
    dmax = max(dmax, __shfl_xor_sync(0xffffffffu, dmax, 8));
    dmax = max(dmax, __shfl_xor_sync(0xffffffffu, dmax, 16));

    for (int base = 0; base < dmax; base += 8) {
        int off = base + c;
        int cl = (deg > 0) ? (e + min(off, deg - 1)) : 0;   // clamped, valid
        int2 ce = g_csr[cl];
        #pragma unroll
        for (int j = 0; j < 8; j++) {
            int  srcn = __shfl_sync(0xffffffffu, ce.x, j, 8);
            int  nrmb = __shfl_sync(0xffffffffu, ce.y, j, 8);
            uint4 v = ((const uint4*)(g_h1h + (size_t)srcn * 32))[c];
            if (base + j < deg) acc8(acc, v, __int_as_float(nrmb));
        }
    }
    #pragma unroll
    for (int i = 0; i < 8; i++)
        acc[i] = fmaxf(acc[i] + b1s[c * 8 + i], 0.f);
    *(float4*)&ts[li][c * 8]     = make_float4(acc[0], acc[1], acc[2], acc[3]);
    *(float4*)&ts[li][c * 8 + 4] = make_float4(acc[4], acc[5], acc[6], acc[7]);
    __syncthreads();

    // gemm2: thread computes feats (2fp, 2fp+1) of node n2; one half2 store
    int n2 = tid >> 3, fp = tid & 7;
    float a0 = 0.f, a1 = 0.f;
    #pragma unroll
    for (int k = 0; k < 64; k += 4) {
        float4 t  = *(const float4*)&ts[n2][k];
        float4 w0 = *(const float4*)&W2t[2 * fp][k];
        float4 w1 = *(const float4*)&W2t[2 * fp + 1][k];
        a0 += t.x * w0.x + t.y * w0.y + t.z * w0.z + t.w * w0.w;
        a1 += t.x * w1.x + t.y * w1.y + t.z * w1.z + t.w * w1.w;
    }
    int gnode = blockIdx.x * 32 + n2;
    if (gnode < N) g_h2h[(size_t)gnode * 8 + fp] = __floats2half2_rn(a0, a1);
}

// ---- k_gather2: gather2 + bias + log_softmax on fp16 h2; zero tail --------
__global__ __launch_bounds__(256) void k_gather2(float* __restrict__ out,
                                                 const float* __restrict__ b2, int N) {
    int tid = threadIdx.x;
    int li = tid >> 2, c2 = tid & 3;
    int node = blockIdx.x * 64 + li;
    bool valid = node < N;
    if (!valid) node = N - 1;

    float di = g_dinv[node];
    float sc = di * di;
    uint2 su = ((const uint2*)(g_h2h + (size_t)node * 8))[c2];
    float2 s0 = __half22float2(*(__half2*)&su.x);
    float2 s1 = __half22float2(*(__half2*)&su.y);
    float4 acc = make_float4(s0.x * sc, s0.y * sc, s1.x * sc, s1.y * sc);

    int e = rowstart(node);
    int deg = g_incnt[node];
    if (valid && c2 == 0) g_incnt[node] = 0;   // zero for next call (after read)
    int dmax = deg;
    dmax = max(dmax, __shfl_xor_sync(0xffffffffu, dmax, 4));
    dmax = max(dmax, __shfl_xor_sync(0xffffffffu, dmax, 8));
    dmax = max(dmax, __shfl_xor_sync(0xffffffffu, dmax, 16));

    for (int base = 0; base < dmax; base += 4) {
        int off = base + c2;
        int cl = (deg > 0) ? (e + min(off, deg - 1)) : 0;
        int2 ce = g_csr[cl];
        #pragma unroll
        for (int j = 0; j < 4; j++) {
            int srcn = __shfl_sync(0xffffffffu, ce.x, j, 4);
            int nrmb = __shfl_sync(0xffffffffu, ce.y, j, 4);
            uint2 vu = ((const uint2*)(g_h2h + (size_t)srcn * 8))[c2];
            if (base + j < deg) {
                float nn = __int_as_float(nrmb);
                float2 f0 = __half22float2(*(__half2*)&vu.x);
                float2 f1 = __half22float2(*(__half2*)&vu.y);
                acc.x += f0.x * nn; acc.y += f0.y * nn;
                acc.z += f1.x * nn; acc.w += f1.y * nn;
            }
        }
    }
    float4 b = ((const float4*)b2)[c2];
    acc.x += b.x; acc.y += b.y; acc.z += b.z; acc.w += b.w;
    float m = fmaxf(fmaxf(acc.x, acc.y), fmaxf(acc.z, acc.w));
    m = fmaxf(m, __shfl_xor_sync(0xffffffffu, m, 1));
    m = fmaxf(m, __shfl_xor_sync(0xffffffffu, m, 2));
    float se = expf(acc.x - m) + expf(acc.y - m) + expf(acc.z - m) + expf(acc.w - m);
    se += __shfl_xor_sync(0xffffffffu, se, 1);
    se += __shfl_xor_sync(0xffffffffu, se, 2);
    float l = m + logf(se);
    acc.x -= l; acc.y -= l; acc.z -= l; acc.w -= l;
    if (valid) ((float4*)(out + (size_t)node * OUT_CH))[c2] = acc;
}

// ---------------------------------------------------------------------------
extern "C" void kernel_launch(void* const* d_in, const int* in_sizes, int n_in,
                              void* d_out, int out_size) {
    const float* x  = (const float*)d_in[0];
    const void*  ei = d_in[1];
    const float* W1 = (const float*)d_in[2];
    const float* b1 = (const float*)d_in[3];
    const float* W2 = (const float*)d_in[4];
    const float* b2 = (const float*)d_in[5];
    float* out = (float*)d_out;

    int N = in_sizes[0] / IN_CH;
    long long E = in_sizes[1] / 2;

    int nwords = (int)((E < 512) ? E : 512);
    int nbS = (N + 255) / 256;
    int nbG = (N + 127) / 128;
    int nchunks = (int)((E + PREP_CHUNK - 1) / PREP_CHUNK);
    int npool = nbG + nchunks;
    if (npool < 4 * nchunks) npool = 4 * nchunks;  // ticket map covers all chunks

    int sms = 148;
    cudaDeviceGetAttribute(&sms, cudaDevAttrMultiProcessorCount, 0);
    int nbar = sms * 6;   // __launch_bounds__(256,6) guarantees co-residency

    k_pool<<<npool, 256>>>(x, ei, W1, N, E, nbG, nchunks, nwords);
    k_fin<<<nbar, 256>>>(N, E, nbS);
    k_g1g2<<<(N + 31) / 32, 256>>>(b1, W2, N);
    k_gather2<<<(N + 63) / 64, 256>>>(out, b2, N);
}